// round 1
// baseline (speedup 1.0000x reference)
#include <cuda_runtime.h>

#define NPTS 100000
#define KC   1024
#define CF   64

typedef unsigned long long ull;

// ---------------- scratch (static __device__, no allocation) ----------------
__device__ float g_P[NPTS * 64];     // per-point layer-1 partials (25.6 MB)
__device__ float g_ct[KC * 64];      // per-centroid layer-1 term (b1 - cent@W1c)
__device__ int   g_idx[KC * KC];     // selected neighbor indices
__device__ int   g_cnt[KC];          // valid neighbor counts

// ---------------- packed f32x2 helpers (sm_103a FFMA2 path) ----------------
__device__ __forceinline__ ull pack2(float lo, float hi) {
    ull r; asm("mov.b64 %0, {%1, %2};" : "=l"(r) : "f"(lo), "f"(hi)); return r;
}
__device__ __forceinline__ void unpack2(ull v, float& lo, float& hi) {
    asm("mov.b64 {%0, %1}, %2;" : "=f"(lo), "=f"(hi) : "l"(v));
}
__device__ __forceinline__ ull fma2(ull a, ull b, ull c) {
    ull d; asm("fma.rn.f32x2 %0, %1, %2, %3;" : "=l"(d) : "l"(a), "l"(b), "l"(c)); return d;
}

// ======================================================================
// Stage A: P[j,:] = coords[j] @ W1[0:3,:] + feats[j] @ W1[3:67,:]
// ======================================================================
__global__ __launch_bounds__(256) void k_P(const float* __restrict__ coords,
                                           const float* __restrict__ feats,
                                           const float* __restrict__ W1)
{
    __shared__ float W1s[67 * 64];
    __shared__ float xs[64 * 68];          // 64 rows, 67 inputs, pitch 68

    const int tid = threadIdx.x;
    const int row0 = blockIdx.x * 64;

    for (int i = tid; i < 67 * 64; i += 256) W1s[i] = W1[i];
    for (int i = tid; i < 64 * 64; i += 256) {
        int r = i >> 6, c = i & 63; int row = row0 + r;
        xs[r * 68 + 3 + c] = (row < NPTS) ? feats[row * 64 + c] : 0.f;
    }
    for (int i = tid; i < 192; i += 256) {
        int r = i / 3, d = i - 3 * r; int row = row0 + r;
        xs[r * 68 + d] = (row < NPTS) ? coords[row * 3 + d] : 0.f;
    }
    __syncthreads();

    const int r = tid >> 2, seg = tid & 3;
    const int row = row0 + r;
    ull acc[8];
    ull z = pack2(0.f, 0.f);
#pragma unroll
    for (int j = 0; j < 8; j++) acc[j] = z;

    const float* xr = &xs[r * 68];
    for (int k = 0; k < 67; k++) {
        float a = xr[k];
        ull A = pack2(a, a);
        const ull* wr = (const ull*)&W1s[k * 64 + seg * 16];
#pragma unroll
        for (int j = 0; j < 8; j++) acc[j] = fma2(A, wr[j], acc[j]);
    }
    if (row < NPTS) {
        ull* dst = (ull*)&g_P[row * 64 + seg * 16];
#pragma unroll
        for (int j = 0; j < 8; j++) dst[j] = acc[j];
    }
}

// ======================================================================
// Stage B1: centroid coords to output + per-centroid layer-1 term
// ======================================================================
__global__ __launch_bounds__(256) void k_cent(const float* __restrict__ coords,
                                              const int* __restrict__ cidx,
                                              const float* __restrict__ W1,
                                              const float* __restrict__ b1,
                                              float* __restrict__ out)
{
    int gid = blockIdx.x * 256 + threadIdx.x;
    if (gid >= KC * 64) return;
    int k = gid >> 6, c = gid & 63;
    int ci = cidx[k];
    float cx = coords[ci * 3 + 0];
    float cy = coords[ci * 3 + 1];
    float cz = coords[ci * 3 + 2];
    g_ct[gid] = b1[c] - (cx * W1[c] + cy * W1[64 + c] + cz * W1[128 + c]);
    if (c < 3) out[k * 3 + c] = coords[ci * 3 + c];
}

// ======================================================================
// Stage B2: ball query — first <=1024 in-radius points in index order,
// with early exit. One block per centroid.
// ======================================================================
__global__ __launch_bounds__(256) void k_ball(const float* __restrict__ coords,
                                              const int* __restrict__ cidx)
{
    __shared__ int wcnt[2][8];
    const int tid = threadIdx.x, bid = blockIdx.x;
    const int w = tid >> 5, l = tid & 31;

    int ci = cidx[bid];
    float cx = coords[ci * 3 + 0];
    float cy = coords[ci * 3 + 1];
    float cz = coords[ci * 3 + 2];
    float cc = cx * cx + cy * cy + cz * cz;

    int total = 0;
    int buf = 0;
    for (int base = 0; base < NPTS; base += 256, buf ^= 1) {
        int j = base + tid;
        bool pred = false;
        if (j < NPTS) {
            float px = coords[3 * j + 0];
            float py = coords[3 * j + 1];
            float pz = coords[3 * j + 2];
            float pp = px * px + py * py + pz * pz;
            // match reference: (||c||^2 + ||p||^2) - 2*(c.p)  <=  f32(0.04)
            float d2 = (cc + pp) - 2.0f * (cx * px + cy * py + cz * pz);
            pred = (d2 <= 0.04f);
        }
        unsigned bal = __ballot_sync(0xffffffffu, pred);
        if (l == 0) wcnt[buf][w] = __popc(bal);
        int csum = __syncthreads_count(pred);       // barrier: wcnt visible, csum = block count
        if (pred) {
            int off = total + __popc(bal & ((1u << l) - 1u));
#pragma unroll
            for (int ww = 0; ww < 8; ww++) off += (ww < w) ? wcnt[buf][ww] : 0;
            if (off < KC) g_idx[bid * KC + off] = j;
        }
        total += csum;                              // identical across all threads
        if (total >= KC) break;                     // uniform break
    }
    if (tid == 0) g_cnt[bid] = (total < KC) ? total : KC;
}

// ======================================================================
// Stage C: per-centroid MLP (layers 2,3) + masked max-pool.
// One block (256 threads) per centroid; packed f32x2 FMA.
// ======================================================================
#define MLP_SMEM_FLOATS 21248   // 84992 bytes

__global__ __launch_bounds__(256, 2) void k_mlp(const float* __restrict__ W2,
                                                const float* __restrict__ b2,
                                                const float* __restrict__ W3,
                                                const float* __restrict__ b3,
                                                float* __restrict__ outF)
{
    extern __shared__ float sm[];
    float* W2s = sm;            // 64*64   = 4096
    float* W3s = sm + 4096;     // 64*128  = 8192
    float* b2s = sm + 12288;    // 64
    float* b3s = sm + 12352;    // 128
    float* cts = sm + 12480;    // 64
    float* h1  = sm + 12544;    // 64*68   = 4352
    float* h2  = sm + 16896;    // 64*68   = 4352

    const int tid = threadIdx.x, bid = blockIdx.x;
    for (int i = tid; i < 4096; i += 256) W2s[i] = W2[i];
    for (int i = tid; i < 8192; i += 256) W3s[i] = W3[i];
    if (tid < 64)  b2s[tid] = b2[tid];
    if (tid < 128) b3s[tid] = b3[tid];
    if (tid < 64)  cts[tid] = g_ct[bid * 64 + tid];
    const int cnt = g_cnt[bid];
    __syncthreads();

    const int rg = tid >> 4, cg = tid & 15;   // GEMM roles: 16x4 rows, cols
    const int gr = tid >> 2, seg = tid & 3;   // gather roles
    const int P1 = 68;

    float rmax[8];
#pragma unroll
    for (int j = 0; j < 8; j++) rmax[j] = 0.f;   // safe: relu>=0, >=1 valid row always

    for (int t = 0; t < 16; t++) {
        if (t * 64 >= cnt) break;               // uniform
        // ---- gather + layer 1 (P[idx] + Ct, relu) -> h1 ----
        {
            int grow = t * 64 + gr;
            float4 v[4];
            if (grow < cnt) {
                int j = g_idx[bid * KC + grow];
                const float4* Pp = (const float4*)(g_P + j * 64 + seg * 16);
#pragma unroll
                for (int q = 0; q < 4; q++) {
                    float4 x = Pp[q];
                    float4 c = *(const float4*)&cts[seg * 16 + q * 4];
                    v[q].x = fmaxf(x.x + c.x, 0.f);
                    v[q].y = fmaxf(x.y + c.y, 0.f);
                    v[q].z = fmaxf(x.z + c.z, 0.f);
                    v[q].w = fmaxf(x.w + c.w, 0.f);
                }
            } else {
#pragma unroll
                for (int q = 0; q < 4; q++) v[q] = make_float4(0.f, 0.f, 0.f, 0.f);
            }
#pragma unroll
            for (int q = 0; q < 4; q++)
                *(float4*)&h1[gr * P1 + seg * 16 + q * 4] = v[q];
        }
        __syncthreads();
        // ---- layer 2: h2 = relu(h1 @ W2 + b2) ----
        {
            ull acc[4][2];
            ull bias0 = *(const ull*)&b2s[cg * 4];
            ull bias1 = *(const ull*)&b2s[cg * 4 + 2];
#pragma unroll
            for (int i = 0; i < 4; i++) { acc[i][0] = bias0; acc[i][1] = bias1; }
#pragma unroll 8
            for (int k = 0; k < 64; k++) {
                ull b0 = *(const ull*)&W2s[k * 64 + cg * 4];
                ull b1v = *(const ull*)&W2s[k * 64 + cg * 4 + 2];
#pragma unroll
                for (int i = 0; i < 4; i++) {
                    float a = h1[(rg * 4 + i) * P1 + k];
                    ull A = pack2(a, a);
                    acc[i][0] = fma2(A, b0, acc[i][0]);
                    acc[i][1] = fma2(A, b1v, acc[i][1]);
                }
            }
#pragma unroll
            for (int i = 0; i < 4; i++) {
                float x0, x1, x2, x3;
                unpack2(acc[i][0], x0, x1);
                unpack2(acc[i][1], x2, x3);
                float4 s = make_float4(fmaxf(x0, 0.f), fmaxf(x1, 0.f),
                                       fmaxf(x2, 0.f), fmaxf(x3, 0.f));
                *(float4*)&h2[(rg * 4 + i) * P1 + cg * 4] = s;
            }
        }
        __syncthreads();
        // ---- layer 3 + masked running max ----
        {
            ull acc[4][4];
            ull bias[4];
#pragma unroll
            for (int j = 0; j < 4; j++) bias[j] = *(const ull*)&b3s[cg * 8 + 2 * j];
#pragma unroll
            for (int i = 0; i < 4; i++)
#pragma unroll
                for (int j = 0; j < 4; j++) acc[i][j] = bias[j];
#pragma unroll 8
            for (int k = 0; k < 64; k++) {
                ull b[4];
#pragma unroll
                for (int j = 0; j < 4; j++) b[j] = *(const ull*)&W3s[k * 128 + cg * 8 + 2 * j];
#pragma unroll
                for (int i = 0; i < 4; i++) {
                    float a = h2[(rg * 4 + i) * P1 + k];
                    ull A = pack2(a, a);
#pragma unroll
                    for (int j = 0; j < 4; j++) acc[i][j] = fma2(A, b[j], acc[i][j]);
                }
            }
#pragma unroll
            for (int i = 0; i < 4; i++) {
                if (t * 64 + rg * 4 + i < cnt) {
#pragma unroll
                    for (int j = 0; j < 4; j++) {
                        float lo, hi; unpack2(acc[i][j], lo, hi);
                        rmax[2 * j]     = fmaxf(rmax[2 * j],     fmaxf(lo, 0.f));
                        rmax[2 * j + 1] = fmaxf(rmax[2 * j + 1], fmaxf(hi, 0.f));
                    }
                }
            }
        }
        __syncthreads();
    }

    // ---- cross-thread column max (16 row-groups -> 1) ----
    __syncthreads();
    float* red = h1;   // reuse (16 x 128 floats)
#pragma unroll
    for (int j = 0; j < 8; j++) red[rg * 128 + cg * 8 + j] = rmax[j];
    __syncthreads();
    if (tid < 128) {
        float m = red[tid];
#pragma unroll
        for (int w = 1; w < 16; w++) m = fmaxf(m, red[w * 128 + tid]);
        outF[bid * 128 + tid] = m;
    }
}

// ======================================================================
extern "C" void kernel_launch(void* const* d_in, const int* in_sizes, int n_in,
                              void* d_out, int out_size)
{
    const float* coords = (const float*)d_in[0];
    const float* feats  = (const float*)d_in[1];
    const int*   cidx   = (const int*)  d_in[2];
    const float* W1 = (const float*)d_in[3];
    const float* b1 = (const float*)d_in[4];
    const float* W2 = (const float*)d_in[5];
    const float* b2 = (const float*)d_in[6];
    const float* W3 = (const float*)d_in[7];
    const float* b3 = (const float*)d_in[8];
    float* out = (float*)d_out;

    cudaFuncSetAttribute((const void*)k_mlp,
                         cudaFuncAttributeMaxDynamicSharedMemorySize,
                         MLP_SMEM_FLOATS * 4);

    k_P   <<<(NPTS + 63) / 64, 256>>>(coords, feats, W1);
    k_cent<<<(KC * 64) / 256, 256>>>(coords, cidx, W1, b1, out);
    k_ball<<<KC, 256>>>(coords, cidx);
    k_mlp <<<KC, 256, MLP_SMEM_FLOATS * 4>>>(W2, b2, W3, b3, out + KC * 3);
}

// round 7
// speedup vs baseline: 1.1568x; 1.1568x over previous
#include <cuda_runtime.h>
#include <cuda_bf16.h>
#include <cstdint>

#define NPTS 100000
#define KC   1024

typedef unsigned long long ull;

// ---------------- scratch (static __device__, no allocation) ----------------
__device__ float g_P[NPTS * 64];     // per-point layer-1 partials
__device__ float g_ct[KC * 64];      // per-centroid layer-1 term (b1 - cent@W1c)
__device__ int   g_idx[KC * KC];     // selected neighbor indices
__device__ int   g_cnt[KC];          // valid neighbor counts
__device__ uint4 g_Wimg[3072];       // swizzled bf16 weight images: W2h[512],W2l[512],W3h[1024],W3l[1024]

// ---------------- helpers ----------------
__device__ __forceinline__ ull pack2(float lo, float hi) {
    ull r; asm("mov.b64 %0, {%1, %2};" : "=l"(r) : "f"(lo), "f"(hi)); return r;
}
__device__ __forceinline__ ull fma2(ull a, ull b, ull c) {
    ull d; asm("fma.rn.f32x2 %0, %1, %2, %3;" : "=l"(d) : "l"(a), "l"(b), "l"(c)); return d;
}
__device__ __forceinline__ uint32_t smem_u32(const void* p) {
    uint32_t a;
    asm("{ .reg .u64 t; cvta.to.shared.u64 t, %1; cvt.u32.u64 %0, t; }" : "=r"(a) : "l"(p));
    return a;
}
__host__ __device__ __forceinline__ uint32_t swz128(uint32_t b) { return b ^ ((b >> 3) & 0x70); }

// bf16 hi/lo split of a float pair, packed as bf16x2 words
__device__ __forceinline__ void split2(float a, float b, uint32_t& hi, uint32_t& lo) {
    __nv_bfloat162 h = __floats2bfloat162_rn(a, b);
    float ra = a - __bfloat162float(h.x);
    float rb = b - __bfloat162float(h.y);
    __nv_bfloat162 l = __floats2bfloat162_rn(ra, rb);
    hi = *reinterpret_cast<uint32_t*>(&h);
    lo = *reinterpret_cast<uint32_t*>(&l);
}

// ---------------- legacy tensor-core primitives (sm_80+, valid on sm_103) ----
__device__ __forceinline__ void ldsm4(uint32_t* r, uint32_t addr) {
    asm volatile("ldmatrix.sync.aligned.m8n8.x4.shared.b16 {%0,%1,%2,%3}, [%4];"
                 : "=r"(r[0]), "=r"(r[1]), "=r"(r[2]), "=r"(r[3]) : "r"(addr));
}
__device__ __forceinline__ void mma_bf16(float* d, const uint32_t* a, const uint32_t* b) {
    asm volatile("mma.sync.aligned.m16n8k16.row.col.f32.bf16.bf16.f32 "
                 "{%0,%1,%2,%3}, {%4,%5,%6,%7}, {%8,%9}, {%0,%1,%2,%3};"
                 : "+f"(d[0]), "+f"(d[1]), "+f"(d[2]), "+f"(d[3])
                 : "r"(a[0]), "r"(a[1]), "r"(a[2]), "r"(a[3]), "r"(b[0]), "r"(b[1]));
}

// ======================================================================
// Stage A: P[j,:] = coords[j] @ W1[0:3,:] + feats[j] @ W1[3:67,:]  (fp32)
// ======================================================================
__global__ __launch_bounds__(256) void k_P(const float* __restrict__ coords,
                                           const float* __restrict__ feats,
                                           const float* __restrict__ W1)
{
    __shared__ float W1s[67 * 64];
    __shared__ float xs[64 * 68];

    const int tid = threadIdx.x;
    const int row0 = blockIdx.x * 64;

    for (int i = tid; i < 67 * 64; i += 256) W1s[i] = W1[i];
    for (int i = tid; i < 64 * 64; i += 256) {
        int r = i >> 6, c = i & 63; int row = row0 + r;
        xs[r * 68 + 3 + c] = (row < NPTS) ? feats[row * 64 + c] : 0.f;
    }
    for (int i = tid; i < 192; i += 256) {
        int r = i / 3, d = i - 3 * r; int row = row0 + r;
        xs[r * 68 + d] = (row < NPTS) ? coords[row * 3 + d] : 0.f;
    }
    __syncthreads();

    const int r = tid >> 2, seg = tid & 3;
    const int row = row0 + r;
    ull acc[8];
    ull z = pack2(0.f, 0.f);
#pragma unroll
    for (int j = 0; j < 8; j++) acc[j] = z;

    const float* xr = &xs[r * 68];
    for (int k = 0; k < 67; k++) {
        float a = xr[k];
        ull A = pack2(a, a);
        const ull* wr = (const ull*)&W1s[k * 64 + seg * 16];
#pragma unroll
        for (int j = 0; j < 8; j++) acc[j] = fma2(A, wr[j], acc[j]);
    }
    if (row < NPTS) {
        ull* dst = (ull*)&g_P[row * 64 + seg * 16];
#pragma unroll
        for (int j = 0; j < 8; j++) dst[j] = acc[j];
    }
}

// ======================================================================
// Stage B1: centroid coords to output + per-centroid layer-1 term
// ======================================================================
__global__ __launch_bounds__(256) void k_cent(const float* __restrict__ coords,
                                              const int* __restrict__ cidx,
                                              const float* __restrict__ W1,
                                              const float* __restrict__ b1,
                                              float* __restrict__ out)
{
    int gid = blockIdx.x * 256 + threadIdx.x;
    if (gid >= KC * 64) return;
    int k = gid >> 6, c = gid & 63;
    int ci = cidx[k];
    float cx = coords[ci * 3 + 0];
    float cy = coords[ci * 3 + 1];
    float cz = coords[ci * 3 + 2];
    g_ct[gid] = b1[c] - (cx * W1[c] + cy * W1[64 + c] + cz * W1[128 + c]);
    if (c < 3) out[k * 3 + c] = coords[ci * 3 + c];
}

// ======================================================================
// Stage B2: weight prep — [n rows][k=64 bf16] hi/lo images, 128B rows,
// SW128-swizzled; directly ldmatrix-able as mma.sync B fragments.
// ======================================================================
__global__ __launch_bounds__(512) void k_prepW(const float* __restrict__ W2,
                                               const float* __restrict__ W3)
{
    const int tid = threadIdx.x;
    // W2 [64k][64n] -> B tile [n=64 rows][k=64] : 512 16B chunks
    if (tid < 512) {
        int c = tid;
        int n = c >> 3, kc = c & 7;
        uint32_t hi[4], lo[4];
#pragma unroll
        for (int q = 0; q < 4; q++) {
            int k0 = kc * 8 + 2 * q;
            split2(W2[k0 * 64 + n], W2[(k0 + 1) * 64 + n], hi[q], lo[q]);
        }
        int dst = swz128(n * 128 + kc * 16) >> 4;
        g_Wimg[dst]       = make_uint4(hi[0], hi[1], hi[2], hi[3]);
        g_Wimg[512 + dst] = make_uint4(lo[0], lo[1], lo[2], lo[3]);
    }
    // W3 [64k][128n] -> B tile [n=128 rows][k=64] : 1024 chunks
    for (int c = tid; c < 1024; c += 512) {
        int n = c >> 3, kc = c & 7;
        uint32_t hi[4], lo[4];
#pragma unroll
        for (int q = 0; q < 4; q++) {
            int k0 = kc * 8 + 2 * q;
            split2(W3[k0 * 128 + n], W3[(k0 + 1) * 128 + n], hi[q], lo[q]);
        }
        int dst = swz128(n * 128 + kc * 16) >> 4;
        g_Wimg[1024 + dst] = make_uint4(hi[0], hi[1], hi[2], hi[3]);
        g_Wimg[2048 + dst] = make_uint4(lo[0], lo[1], lo[2], lo[3]);
    }
}

// ======================================================================
// Stage C1: ball query — one WARP per centroid, 8 centroids/block,
// coords staged through shared memory (read once per block from L2).
// ======================================================================
#define BALL_TILE 2048

__global__ __launch_bounds__(256) void k_ball(const float* __restrict__ coords,
                                              const int* __restrict__ cidx)
{
    __shared__ float xs[BALL_TILE], ys[BALL_TILE], zs[BALL_TILE];
    const int tid = threadIdx.x;
    const int w = tid >> 5, l = tid & 31;
    const int cid = blockIdx.x * 8 + w;

    int ci = cidx[cid];
    float cx = coords[ci * 3 + 0];
    float cy = coords[ci * 3 + 1];
    float cz = coords[ci * 3 + 2];
    float cc = cx * cx + cy * cy + cz * cz;

    int total = 0;
    bool done = false;

    for (int base = 0; base < NPTS; base += BALL_TILE) {
        int nv = (NPTS - base < BALL_TILE ? NPTS - base : BALL_TILE) * 3;
        for (int v = tid; v < BALL_TILE * 3; v += 256) {
            float f = (v < nv) ? coords[base * 3 + v] : 1e9f;
            int p = v / 3, d = v - 3 * p;
            if (d == 0) xs[p] = f; else if (d == 1) ys[p] = f; else zs[p] = f;
        }
        __syncthreads();

        if (!done) {
            for (int i = l; i < BALL_TILE; i += 32) {
                float px = xs[i], py = ys[i], pz = zs[i];
                float pp = px * px + py * py + pz * pz;
                float d2 = (cc + pp) - 2.0f * (cx * px + cy * py + cz * pz);
                bool pred = (d2 <= 0.04f);
                unsigned bal = __ballot_sync(0xffffffffu, pred);
                if (pred) {
                    int off = total + __popc(bal & ((1u << l) - 1u));
                    if (off < KC) g_idx[cid * KC + off] = base + i;
                }
                total += __popc(bal);
                if (total >= KC) break;
            }
            if (total >= KC) done = true;
        }
        if (__syncthreads_and(done ? 1 : 0)) break;
        __syncthreads();
    }
    if (l == 0) g_cnt[cid] = (total < KC) ? total : KC;
}

// ======================================================================
// Stage D: per-centroid MLP via mma.sync bf16 hi/lo split (3-pass),
// fp32 accumulation. One 512-thread block per centroid, 128-row tiles.
// Warp w (0-15): rows (w%8)*16; layer2 cols (w/8)*32; layer3 cols (w/8)*64.
// ======================================================================
#define SM_AH  0          // [128 m][64 k] bf16 hi, 128B rows, swizzled (16KB)
#define SM_AL  16384      // lo (16KB)
#define SM_W   32768      // W2h 8K | W2l 8K | W3h 16K | W3l 16K  -> ends 81920
#define SM_CT  81920
#define SM_B2  82176
#define SM_B3  82432
#define SM_RED 82944      // 8 x 128 floats (4KB)
#define SM_TOTAL 87040

__global__ void __launch_bounds__(512, 1)
k_mlp(const float* __restrict__ b2g, const float* __restrict__ b3g,
      float* __restrict__ outF)
{
    extern __shared__ char sm[];
    const uint32_t sb = smem_u32(sm);
    const int tid = threadIdx.x, bid = blockIdx.x;
    const int w = tid >> 5, lane = tid & 31;

    {   // weight + bias + ct staging
        uint4* dst = (uint4*)(sm + SM_W);
        for (int i = tid; i < 3072; i += 512) dst[i] = g_Wimg[i];
        if (tid < 64)       ((float*)(sm + SM_CT))[tid] = g_ct[bid * 64 + tid];
        else if (tid < 128) ((float*)(sm + SM_B2))[tid - 64] = b2g[tid - 64];
        else if (tid < 256) ((float*)(sm + SM_B3))[tid - 128] = b3g[tid - 128];
    }
    const int cnt = g_cnt[bid];
    __syncthreads();

    const int gr = tid >> 2, gseg = tid & 3;        // gather roles (128 rows x 4 segs)
    const float* cts = (const float*)(sm + SM_CT);
    const float* b2s = (const float*)(sm + SM_B2);
    const float* b3s = (const float*)(sm + SM_B3);

    const int mrow = (w & 7) * 16;
    const int nc2  = (w >> 3) * 32;
    const int nc3  = (w >> 3) * 64;
    // ldmatrix lane address components
    const uint32_t a_row  = mrow + (lane & 15);
    const uint32_t a_half = ((lane >> 4) & 1) * 16;          // k-half byte offset
    const uint32_t b_nrow = (lane & 7) + ((lane >> 4) & 1) * 8;  // quadrant bit1 -> n+8
    const uint32_t b_koff = ((lane >> 3) & 1) * 16;              // quadrant bit0 -> k+8

    float rmax[16];
#pragma unroll
    for (int i = 0; i < 16; i++) rmax[i] = 0.f;   // relu >= 0, row 0 always valid

    for (int t = 0; t * 128 < cnt; t++) {
        // ---- gather + layer1 (relu(P[idx]+ct)), bf16-split -> Ah/Al ----
        {
            const int row = t * 128 + gr;
            float x[16];
            if (row < cnt) {
                int j = g_idx[bid * KC + row];
                const float4* Pp = (const float4*)(g_P + j * 64 + gseg * 16);
#pragma unroll
                for (int q = 0; q < 4; q++) {
                    float4 v = __ldg(Pp + q);
                    float4 c = *(const float4*)&cts[gseg * 16 + q * 4];
                    x[q * 4 + 0] = fmaxf(v.x + c.x, 0.f);
                    x[q * 4 + 1] = fmaxf(v.y + c.y, 0.f);
                    x[q * 4 + 2] = fmaxf(v.z + c.z, 0.f);
                    x[q * 4 + 3] = fmaxf(v.w + c.w, 0.f);
                }
            } else {
#pragma unroll
                for (int i = 0; i < 16; i++) x[i] = 0.f;
            }
            uint32_t hi[8], lo[8];
#pragma unroll
            for (int q = 0; q < 8; q++) split2(x[2 * q], x[2 * q + 1], hi[q], lo[q]);
            uint32_t b0 = gr * 128 + gseg * 32;
            uint32_t s0 = swz128(b0), s1 = swz128(b0 + 16);
            *(uint4*)(sm + SM_AH + s0) = make_uint4(hi[0], hi[1], hi[2], hi[3]);
            *(uint4*)(sm + SM_AH + s1) = make_uint4(hi[4], hi[5], hi[6], hi[7]);
            *(uint4*)(sm + SM_AL + s0) = make_uint4(lo[0], lo[1], lo[2], lo[3]);
            *(uint4*)(sm + SM_AL + s1) = make_uint4(lo[4], lo[5], lo[6], lo[7]);
        }
        __syncthreads();

        // ---- A fragments (h1) ----
        uint32_t Ah[4][4], Al[4][4];
#pragma unroll
        for (int kt = 0; kt < 4; kt++) {
            uint32_t off = swz128(a_row * 128 + kt * 32 + a_half);
            ldsm4(Ah[kt], sb + SM_AH + off);
            ldsm4(Al[kt], sb + SM_AL + off);
        }
        __syncthreads();   // all h1 reads done before epilogue2 overwrites

        // ---- layer2: D[128x64] (per warp 16x32), 3-pass bf16 ----
        float D[4][4];
#pragma unroll
        for (int i = 0; i < 4; i++)
#pragma unroll
            for (int j = 0; j < 4; j++) D[i][j] = 0.f;
#pragma unroll
        for (int p = 0; p < 2; p++) {
#pragma unroll
            for (int kt = 0; kt < 4; kt++) {
                uint32_t off = swz128((nc2 + p * 16 + b_nrow) * 128 + kt * 32 + b_koff);
                uint32_t Bh[4], Bl[4];
                ldsm4(Bh, sb + SM_W + off);
                ldsm4(Bl, sb + SM_W + 8192 + off);
                mma_bf16(D[p * 2 + 0], Ah[kt], Bh + 0);
                mma_bf16(D[p * 2 + 0], Al[kt], Bh + 0);
                mma_bf16(D[p * 2 + 0], Ah[kt], Bl + 0);
                mma_bf16(D[p * 2 + 1], Ah[kt], Bh + 2);
                mma_bf16(D[p * 2 + 1], Al[kt], Bh + 2);
                mma_bf16(D[p * 2 + 1], Ah[kt], Bl + 2);
            }
        }

        // ---- epilogue2: relu(D+b2), split, store h2 into Ah/Al ----
        {
            const int r0 = mrow + (lane >> 2);
            const int jc = (lane & 3) * 2;
#pragma unroll
            for (int nt = 0; nt < 4; nt++) {
                int j0 = nc2 + nt * 8 + jc;
                float v0 = fmaxf(D[nt][0] + b2s[j0],     0.f);
                float v1 = fmaxf(D[nt][1] + b2s[j0 + 1], 0.f);
                float v2 = fmaxf(D[nt][2] + b2s[j0],     0.f);
                float v3 = fmaxf(D[nt][3] + b2s[j0 + 1], 0.f);
                uint32_t h0, l0, h1, l1;
                split2(v0, v1, h0, l0);
                split2(v2, v3, h1, l1);
                uint32_t o0 = swz128(r0 * 128 + j0 * 2);
                uint32_t o1 = swz128((r0 + 8) * 128 + j0 * 2);
                *(uint32_t*)(sm + SM_AH + o0) = h0;
                *(uint32_t*)(sm + SM_AL + o0) = l0;
                *(uint32_t*)(sm + SM_AH + o1) = h1;
                *(uint32_t*)(sm + SM_AL + o1) = l1;
            }
        }
        __syncthreads();

        // ---- A fragments (h2) ----
#pragma unroll
        for (int kt = 0; kt < 4; kt++) {
            uint32_t off = swz128(a_row * 128 + kt * 32 + a_half);
            ldsm4(Ah[kt], sb + SM_AH + off);
            ldsm4(Al[kt], sb + SM_AL + off);
        }
        __syncthreads();   // all h2 reads done before next gather overwrites

        // ---- layer3 (per warp 16x64, two 32-col halves) + masked max ----
        const int r0g = t * 128 + mrow + (lane >> 2);
        const bool vr0 = (r0g < cnt), vr1 = (r0g + 8 < cnt);
#pragma unroll
        for (int hh = 0; hh < 2; hh++) {
            float D3[4][4];
#pragma unroll
            for (int i = 0; i < 4; i++)
#pragma unroll
                for (int j = 0; j < 4; j++) D3[i][j] = 0.f;
#pragma unroll
            for (int p = 0; p < 2; p++) {
#pragma unroll
                for (int kt = 0; kt < 4; kt++) {
                    uint32_t off = swz128((nc3 + hh * 32 + p * 16 + b_nrow) * 128 + kt * 32 + b_koff);
                    uint32_t Bh[4], Bl[4];
                    ldsm4(Bh, sb + SM_W + 16384 + off);
                    ldsm4(Bl, sb + SM_W + 32768 + off);
                    mma_bf16(D3[p * 2 + 0], Ah[kt], Bh + 0);
                    mma_bf16(D3[p * 2 + 0], Al[kt], Bh + 0);
                    mma_bf16(D3[p * 2 + 0], Ah[kt], Bl + 0);
                    mma_bf16(D3[p * 2 + 1], Ah[kt], Bh + 2);
                    mma_bf16(D3[p * 2 + 1], Al[kt], Bh + 2);
                    mma_bf16(D3[p * 2 + 1], Ah[kt], Bl + 2);
                }
            }
            const int jc = (lane & 3) * 2;
#pragma unroll
            for (int nt = 0; nt < 4; nt++) {
                int j0 = nc3 + hh * 32 + nt * 8 + jc;
                int ri = hh * 8 + nt * 2;
                if (vr0) {
                    rmax[ri]     = fmaxf(rmax[ri],     fmaxf(D3[nt][0] + b3s[j0],     0.f));
                    rmax[ri + 1] = fmaxf(rmax[ri + 1], fmaxf(D3[nt][1] + b3s[j0 + 1], 0.f));
                }
                if (vr1) {
                    rmax[ri]     = fmaxf(rmax[ri],     fmaxf(D3[nt][2] + b3s[j0],     0.f));
                    rmax[ri + 1] = fmaxf(rmax[ri + 1], fmaxf(D3[nt][3] + b3s[j0 + 1], 0.f));
                }
            }
        }
    }

    // ---- reduce: lanes sharing lane%4 hold same cols -> butterfly ----
#pragma unroll
    for (int o = 4; o <= 16; o <<= 1)
#pragma unroll
        for (int i = 0; i < 16; i++)
            rmax[i] = fmaxf(rmax[i], __shfl_xor_sync(0xffffffffu, rmax[i], o));
    if (lane < 4) {
        float* red = (float*)(sm + SM_RED);
#pragma unroll
        for (int i = 0; i < 16; i++) {
            int col = nc3 + (i >> 1) * 8 + lane * 2 + (i & 1);
            red[(w & 7) * 128 + col] = rmax[i];
        }
    }
    __syncthreads();
    if (tid < 128) {
        const float* red = (const float*)(sm + SM_RED);
        float m = red[tid];
#pragma unroll
        for (int r = 1; r < 8; r++) m = fmaxf(m, red[r * 128 + tid]);
        outF[bid * 128 + tid] = m;
    }
}

// ======================================================================
extern "C" void kernel_launch(void* const* d_in, const int* in_sizes, int n_in,
                              void* d_out, int out_size)
{
    const float* coords = (const float*)d_in[0];
    const float* feats  = (const float*)d_in[1];
    const int*   cidx   = (const int*)  d_in[2];
    const float* W1 = (const float*)d_in[3];
    const float* b1 = (const float*)d_in[4];
    const float* W2 = (const float*)d_in[5];
    const float* b2 = (const float*)d_in[6];
    const float* W3 = (const float*)d_in[7];
    const float* b3 = (const float*)d_in[8];
    float* out = (float*)d_out;

    cudaFuncSetAttribute((const void*)k_mlp,
                         cudaFuncAttributeMaxDynamicSharedMemorySize, SM_TOTAL);

    k_P    <<<(NPTS + 63) / 64, 256>>>(coords, feats, W1);
    k_cent <<<(KC * 64) / 256, 256>>>(coords, cidx, W1, b1, out);
    k_prepW<<<1, 512>>>(W2, W3);
    k_ball <<<KC / 8, 256>>>(coords, cidx);
    k_mlp  <<<KC, 512, SM_TOTAL>>>(b2, b3, out + KC * 3);
}

// round 10
// speedup vs baseline: 1.6506x; 1.4269x over previous
#include <cuda_runtime.h>
#include <cuda_bf16.h>
#include <cstdint>

#define NPTS 100000
#define KC   1024
#define NPAD 100352            // 49 * 2048

typedef unsigned long long ull;

// ---------------- scratch (static __device__, no allocation) ----------------
__device__ float g_P[NPTS * 64];     // per-point layer-1 partials
__device__ float g_ct[KC * 64];      // per-centroid layer-1 term (b1 - cent@W1c)
__device__ int   g_idx[KC * KC];     // selected neighbor indices
__device__ int   g_cnt[KC];          // valid neighbor counts
__device__ uint4 g_Wimg[3072];       // swizzled bf16 weight images
__device__ float4 g_pts[NPAD];       // packed (x,y,z,||p||^2), padded with sentinels

// ---------------- helpers ----------------
__device__ __forceinline__ ull pack2(float lo, float hi) {
    ull r; asm("mov.b64 %0, {%1, %2};" : "=l"(r) : "f"(lo), "f"(hi)); return r;
}
__device__ __forceinline__ ull fma2(ull a, ull b, ull c) {
    ull d; asm("fma.rn.f32x2 %0, %1, %2, %3;" : "=l"(d) : "l"(a), "l"(b), "l"(c)); return d;
}
__device__ __forceinline__ uint32_t smem_u32(const void* p) {
    uint32_t a;
    asm("{ .reg .u64 t; cvta.to.shared.u64 t, %1; cvt.u32.u64 %0, t; }" : "=r"(a) : "l"(p));
    return a;
}
__host__ __device__ __forceinline__ uint32_t swz128(uint32_t b) { return b ^ ((b >> 3) & 0x70); }

// bf16 hi/lo split of a float pair, packed as bf16x2 words
__device__ __forceinline__ void split2(float a, float b, uint32_t& hi, uint32_t& lo) {
    __nv_bfloat162 h = __floats2bfloat162_rn(a, b);
    float ra = a - __bfloat162float(h.x);
    float rb = b - __bfloat162float(h.y);
    __nv_bfloat162 l = __floats2bfloat162_rn(ra, rb);
    hi = *reinterpret_cast<uint32_t*>(&h);
    lo = *reinterpret_cast<uint32_t*>(&l);
}

// ---------------- legacy tensor-core primitives (sm_80+, valid on sm_103) ----
__device__ __forceinline__ void ldsm4(uint32_t* r, uint32_t addr) {
    asm volatile("ldmatrix.sync.aligned.m8n8.x4.shared.b16 {%0,%1,%2,%3}, [%4];"
                 : "=r"(r[0]), "=r"(r[1]), "=r"(r[2]), "=r"(r[3]) : "r"(addr));
}
__device__ __forceinline__ void mma_bf16(float* d, const uint32_t* a, const uint32_t* b) {
    asm volatile("mma.sync.aligned.m16n8k16.row.col.f32.bf16.bf16.f32 "
                 "{%0,%1,%2,%3}, {%4,%5,%6,%7}, {%8,%9}, {%0,%1,%2,%3};"
                 : "+f"(d[0]), "+f"(d[1]), "+f"(d[2]), "+f"(d[3])
                 : "r"(a[0]), "r"(a[1]), "r"(a[2]), "r"(a[3]), "r"(b[0]), "r"(b[1]));
}

// ======================================================================
// Stage A0: pack coords + squared norm, padded with far sentinels
// ======================================================================
__global__ __launch_bounds__(256) void k_pack(const float* __restrict__ coords)
{
    int i = blockIdx.x * 256 + threadIdx.x;
    if (i >= NPAD) return;
    float4 v;
    if (i < NPTS) {
        float x = coords[3 * i], y = coords[3 * i + 1], z = coords[3 * i + 2];
        v = make_float4(x, y, z, x * x + y * y + z * z);
    } else {
        v = make_float4(1e9f, 1e9f, 1e9f, 1e9f);
    }
    g_pts[i] = v;
}

// ======================================================================
// Stage A: P[j,:] = coords[j] @ W1[0:3,:] + feats[j] @ W1[3:67,:]  (fp32)
// ======================================================================
__global__ __launch_bounds__(256) void k_P(const float* __restrict__ coords,
                                           const float* __restrict__ feats,
                                           const float* __restrict__ W1)
{
    __shared__ float W1s[67 * 64];
    __shared__ float xs[64 * 68];

    const int tid = threadIdx.x;
    const int row0 = blockIdx.x * 64;

    for (int i = tid; i < 67 * 64; i += 256) W1s[i] = W1[i];
    for (int i = tid; i < 64 * 64; i += 256) {
        int r = i >> 6, c = i & 63; int row = row0 + r;
        xs[r * 68 + 3 + c] = (row < NPTS) ? feats[row * 64 + c] : 0.f;
    }
    for (int i = tid; i < 192; i += 256) {
        int r = i / 3, d = i - 3 * r; int row = row0 + r;
        xs[r * 68 + d] = (row < NPTS) ? coords[row * 3 + d] : 0.f;
    }
    __syncthreads();

    const int r = tid >> 2, seg = tid & 3;
    const int row = row0 + r;
    ull acc[8];
    ull z = pack2(0.f, 0.f);
#pragma unroll
    for (int j = 0; j < 8; j++) acc[j] = z;

    const float* xr = &xs[r * 68];
    for (int k = 0; k < 67; k++) {
        float a = xr[k];
        ull A = pack2(a, a);
        const ull* wr = (const ull*)&W1s[k * 64 + seg * 16];
#pragma unroll
        for (int j = 0; j < 8; j++) acc[j] = fma2(A, wr[j], acc[j]);
    }
    if (row < NPTS) {
        ull* dst = (ull*)&g_P[row * 64 + seg * 16];
#pragma unroll
        for (int j = 0; j < 8; j++) dst[j] = acc[j];
    }
}

// ======================================================================
// Stage B1: centroid coords to output + per-centroid layer-1 term
// ======================================================================
__global__ __launch_bounds__(256) void k_cent(const float* __restrict__ coords,
                                              const int* __restrict__ cidx,
                                              const float* __restrict__ W1,
                                              const float* __restrict__ b1,
                                              float* __restrict__ out)
{
    int gid = blockIdx.x * 256 + threadIdx.x;
    if (gid >= KC * 64) return;
    int k = gid >> 6, c = gid & 63;
    int ci = cidx[k];
    float cx = coords[ci * 3 + 0];
    float cy = coords[ci * 3 + 1];
    float cz = coords[ci * 3 + 2];
    g_ct[gid] = b1[c] - (cx * W1[c] + cy * W1[64 + c] + cz * W1[128 + c]);
    if (c < 3) out[k * 3 + c] = coords[ci * 3 + c];
}

// ======================================================================
// Stage B2: weight prep — [n rows][k=64 bf16] hi/lo images, 128B rows,
// SW128-swizzled; directly ldmatrix-able as mma.sync B fragments.
// ======================================================================
__global__ __launch_bounds__(512) void k_prepW(const float* __restrict__ W2,
                                               const float* __restrict__ W3)
{
    const int tid = threadIdx.x;
    if (tid < 512) {
        int c = tid;
        int n = c >> 3, kc = c & 7;
        uint32_t hi[4], lo[4];
#pragma unroll
        for (int q = 0; q < 4; q++) {
            int k0 = kc * 8 + 2 * q;
            split2(W2[k0 * 64 + n], W2[(k0 + 1) * 64 + n], hi[q], lo[q]);
        }
        int dst = swz128(n * 128 + kc * 16) >> 4;
        g_Wimg[dst]       = make_uint4(hi[0], hi[1], hi[2], hi[3]);
        g_Wimg[512 + dst] = make_uint4(lo[0], lo[1], lo[2], lo[3]);
    }
    for (int c = tid; c < 1024; c += 512) {
        int n = c >> 3, kc = c & 7;
        uint32_t hi[4], lo[4];
#pragma unroll
        for (int q = 0; q < 4; q++) {
            int k0 = kc * 8 + 2 * q;
            split2(W3[k0 * 128 + n], W3[(k0 + 1) * 128 + n], hi[q], lo[q]);
        }
        int dst = swz128(n * 128 + kc * 16) >> 4;
        g_Wimg[1024 + dst] = make_uint4(hi[0], hi[1], hi[2], hi[3]);
        g_Wimg[2048 + dst] = make_uint4(lo[0], lo[1], lo[2], lo[3]);
    }
}

// ======================================================================
// Stage C1: ball query — warp per centroid, 8 per block, 3-phase tiles:
// (1) 64 independent ballots, (2) one shfl prefix-scan, (3) independent
// writes. FIX vs R8: word fetch for the prefix shuffles BOTH registers
// from the source lane, then selects with the READER's lane id (shfl
// returns the source lane's evaluation of the expression).
// ======================================================================
#define BT 2048

__global__ __launch_bounds__(256) void k_ball(const float* __restrict__ coords,
                                              const int* __restrict__ cidx)
{
    __shared__ float4 tile[BT];
    const int tid = threadIdx.x;
    const int w = tid >> 5, l = tid & 31;
    const int cid = blockIdx.x * 8 + w;

    int ci = cidx[cid];
    float cx = coords[ci * 3 + 0];
    float cy = coords[ci * 3 + 1];
    float cz = coords[ci * 3 + 2];
    float cc = cx * cx + cy * cy + cz * cz;

    int total = 0;
    bool done = false;

    for (int base = 0; base < NPAD; base += BT) {
        // ---- stage tile (8 x LDG.128 / thread) ----
        for (int v = tid; v < BT; v += 256) tile[v] = g_pts[base + v];
        __syncthreads();

        if (!done) {
            // ---- phase 1: 64 independent ballots; word i kept by lane i%32 ----
            uint32_t r0 = 0, r1 = 0;
#pragma unroll
            for (int i = 0; i < 64; i++) {
                float4 p = tile[i * 32 + l];
                float dot = cx * p.x + cy * p.y + cz * p.z;
                float d2 = (cc + p.w) - 2.0f * dot;
                unsigned bal = __ballot_sync(0xffffffffu, d2 <= 0.04f);
                if (i < 32) { if (l == i) r0 = bal; }
                else        { if (l == i - 32) r1 = bal; }
            }
            // ---- phase 2: prefix over 64 word-popcounts (lane l: words 2l,2l+1) ----
            // word 2l lives in r0[2l] (l<16) or r1[2l-32] (l>=16); shuffle both,
            // select with the reader's l (NOT inside the shfl operand).
            uint32_t sa0 = __shfl_sync(0xffffffffu, r0, (2 * l) & 31);
            uint32_t sa1 = __shfl_sync(0xffffffffu, r1, (2 * l) & 31);
            uint32_t sb0 = __shfl_sync(0xffffffffu, r0, (2 * l + 1) & 31);
            uint32_t sb1 = __shfl_sync(0xffffffffu, r1, (2 * l + 1) & 31);
            uint32_t w0 = (l < 16) ? sa0 : sa1;
            uint32_t w1 = (l < 16) ? sb0 : sb1;
            int c0 = __popc(w0), c1 = __popc(w1);
            int s = c0 + c1, incl = s;
#pragma unroll
            for (int o = 1; o < 32; o <<= 1) {
                int t2 = __shfl_up_sync(0xffffffffu, incl, o);
                if (l >= o) incl += t2;
            }
            int b0 = total + incl - s;        // base of word 2l
            int b1v = b0 + c0;                // base of word 2l+1
            int tile_total = __shfl_sync(0xffffffffu, incl, 31);
            // live word count (bases are monotone non-decreasing)
            int nlive = __popc(__ballot_sync(0xffffffffu, b0 < KC))
                      + __popc(__ballot_sync(0xffffffffu, b1v < KC));
            // ---- phase 3: independent writes (selectors i<32, i&1 are uniform) ----
#pragma unroll 8
            for (int i = 0; i < 64; i++) {
                if (i >= nlive) break;
                unsigned bal = __shfl_sync(0xffffffffu, (i < 32) ? r0 : r1, i & 31);
                int b = __shfl_sync(0xffffffffu, (i & 1) ? b1v : b0, i >> 1);
                if ((bal >> l) & 1u) {
                    int off = b + __popc(bal & ((1u << l) - 1u));
                    if (off < KC) g_idx[cid * KC + off] = base + i * 32 + l;
                }
            }
            total += tile_total;
            if (total >= KC) done = true;
        }
        if (__syncthreads_and(done ? 1 : 0)) break;
    }
    if (l == 0) g_cnt[cid] = (total < KC) ? total : KC;
}

// ======================================================================
// Stage D: per-centroid MLP via mma.sync bf16 hi/lo split (3-pass),
// fp32 accumulation. One 512-thread block per centroid, 128-row tiles.
// ======================================================================
#define SM_AH  0          // [128 m][64 k] bf16 hi, 128B rows, swizzled (16KB)
#define SM_AL  16384      // lo (16KB)
#define SM_W   32768      // W2h 8K | W2l 8K | W3h 16K | W3l 16K  -> ends 81920
#define SM_CT  81920
#define SM_B2  82176
#define SM_B3  82432
#define SM_RED 82944      // 8 x 128 floats (4KB)
#define SM_TOTAL 87040

__global__ void __launch_bounds__(512, 1)
k_mlp(const float* __restrict__ b2g, const float* __restrict__ b3g,
      float* __restrict__ outF)
{
    extern __shared__ char sm[];
    const uint32_t sb = smem_u32(sm);
    const int tid = threadIdx.x, bid = blockIdx.x;
    const int w = tid >> 5, lane = tid & 31;

    {   // weight + bias + ct staging
        uint4* dst = (uint4*)(sm + SM_W);
        for (int i = tid; i < 3072; i += 512) dst[i] = g_Wimg[i];
        if (tid < 64)       ((float*)(sm + SM_CT))[tid] = g_ct[bid * 64 + tid];
        else if (tid < 128) ((float*)(sm + SM_B2))[tid - 64] = b2g[tid - 64];
        else if (tid < 256) ((float*)(sm + SM_B3))[tid - 128] = b3g[tid - 128];
    }
    const int cnt = g_cnt[bid];
    __syncthreads();

    const int gr = tid >> 2, gseg = tid & 3;
    const float* cts = (const float*)(sm + SM_CT);
    const float* b2s = (const float*)(sm + SM_B2);
    const float* b3s = (const float*)(sm + SM_B3);

    const int mrow = (w & 7) * 16;
    const int nc2  = (w >> 3) * 32;
    const int nc3  = (w >> 3) * 64;
    const uint32_t a_row  = mrow + (lane & 15);
    const uint32_t a_half = ((lane >> 4) & 1) * 16;
    const uint32_t b_nrow = (lane & 7) + ((lane >> 4) & 1) * 8;
    const uint32_t b_koff = ((lane >> 3) & 1) * 16;

    float rmax[16];
#pragma unroll
    for (int i = 0; i < 16; i++) rmax[i] = 0.f;

    for (int t = 0; t * 128 < cnt; t++) {
        // ---- gather + layer1 (relu(P[idx]+ct)), bf16-split -> Ah/Al ----
        {
            const int row = t * 128 + gr;
            float x[16];
            if (row < cnt) {
                int j = g_idx[bid * KC + row];
                const float4* Pp = (const float4*)(g_P + j * 64 + gseg * 16);
#pragma unroll
                for (int q = 0; q < 4; q++) {
                    float4 v = __ldg(Pp + q);
                    float4 c = *(const float4*)&cts[gseg * 16 + q * 4];
                    x[q * 4 + 0] = fmaxf(v.x + c.x, 0.f);
                    x[q * 4 + 1] = fmaxf(v.y + c.y, 0.f);
                    x[q * 4 + 2] = fmaxf(v.z + c.z, 0.f);
                    x[q * 4 + 3] = fmaxf(v.w + c.w, 0.f);
                }
            } else {
#pragma unroll
                for (int i = 0; i < 16; i++) x[i] = 0.f;
            }
            uint32_t hi[8], lo[8];
#pragma unroll
            for (int q = 0; q < 8; q++) split2(x[2 * q], x[2 * q + 1], hi[q], lo[q]);
            uint32_t b0 = gr * 128 + gseg * 32;
            uint32_t s0 = swz128(b0), s1 = swz128(b0 + 16);
            *(uint4*)(sm + SM_AH + s0) = make_uint4(hi[0], hi[1], hi[2], hi[3]);
            *(uint4*)(sm + SM_AH + s1) = make_uint4(hi[4], hi[5], hi[6], hi[7]);
            *(uint4*)(sm + SM_AL + s0) = make_uint4(lo[0], lo[1], lo[2], lo[3]);
            *(uint4*)(sm + SM_AL + s1) = make_uint4(lo[4], lo[5], lo[6], lo[7]);
        }
        __syncthreads();

        // ---- A fragments (h1) ----
        uint32_t Ah[4][4], Al[4][4];
#pragma unroll
        for (int kt = 0; kt < 4; kt++) {
            uint32_t off = swz128(a_row * 128 + kt * 32 + a_half);
            ldsm4(Ah[kt], sb + SM_AH + off);
            ldsm4(Al[kt], sb + SM_AL + off);
        }
        __syncthreads();

        // ---- layer2: per warp 16x32, 3-pass bf16 ----
        float D[4][4];
#pragma unroll
        for (int i = 0; i < 4; i++)
#pragma unroll
            for (int j = 0; j < 4; j++) D[i][j] = 0.f;
#pragma unroll
        for (int p = 0; p < 2; p++) {
#pragma unroll
            for (int kt = 0; kt < 4; kt++) {
                uint32_t off = swz128((nc2 + p * 16 + b_nrow) * 128 + kt * 32 + b_koff);
                uint32_t Bh[4], Bl[4];
                ldsm4(Bh, sb + SM_W + off);
                ldsm4(Bl, sb + SM_W + 8192 + off);
                mma_bf16(D[p * 2 + 0], Ah[kt], Bh + 0);
                mma_bf16(D[p * 2 + 0], Al[kt], Bh + 0);
                mma_bf16(D[p * 2 + 0], Ah[kt], Bl + 0);
                mma_bf16(D[p * 2 + 1], Ah[kt], Bh + 2);
                mma_bf16(D[p * 2 + 1], Al[kt], Bh + 2);
                mma_bf16(D[p * 2 + 1], Ah[kt], Bl + 2);
            }
        }

        // ---- epilogue2: relu(D+b2), split, store h2 into Ah/Al ----
        {
            const int r0 = mrow + (lane >> 2);
            const int jc = (lane & 3) * 2;
#pragma unroll
            for (int nt = 0; nt < 4; nt++) {
                int j0 = nc2 + nt * 8 + jc;
                float v0 = fmaxf(D[nt][0] + b2s[j0],     0.f);
                float v1 = fmaxf(D[nt][1] + b2s[j0 + 1], 0.f);
                float v2 = fmaxf(D[nt][2] + b2s[j0],     0.f);
                float v3 = fmaxf(D[nt][3] + b2s[j0 + 1], 0.f);
                uint32_t h0, l0, h1, l1;
                split2(v0, v1, h0, l0);
                split2(v2, v3, h1, l1);
                uint32_t o0 = swz128(r0 * 128 + j0 * 2);
                uint32_t o1 = swz128((r0 + 8) * 128 + j0 * 2);
                *(uint32_t*)(sm + SM_AH + o0) = h0;
                *(uint32_t*)(sm + SM_AL + o0) = l0;
                *(uint32_t*)(sm + SM_AH + o1) = h1;
                *(uint32_t*)(sm + SM_AL + o1) = l1;
            }
        }
        __syncthreads();

        // ---- A fragments (h2) ----
#pragma unroll
        for (int kt = 0; kt < 4; kt++) {
            uint32_t off = swz128(a_row * 128 + kt * 32 + a_half);
            ldsm4(Ah[kt], sb + SM_AH + off);
            ldsm4(Al[kt], sb + SM_AL + off);
        }
        __syncthreads();

        // ---- layer3 (per warp 16x64, two 32-col halves) + masked max ----
        const int r0g = t * 128 + mrow + (lane >> 2);
        const bool vr0 = (r0g < cnt), vr1 = (r0g + 8 < cnt);
#pragma unroll
        for (int hh = 0; hh < 2; hh++) {
            float D3[4][4];
#pragma unroll
            for (int i = 0; i < 4; i++)
#pragma unroll
                for (int j = 0; j < 4; j++) D3[i][j] = 0.f;
#pragma unroll
            for (int p = 0; p < 2; p++) {
#pragma unroll
                for (int kt = 0; kt < 4; kt++) {
                    uint32_t off = swz128((nc3 + hh * 32 + p * 16 + b_nrow) * 128 + kt * 32 + b_koff);
                    uint32_t Bh[4], Bl[4];
                    ldsm4(Bh, sb + SM_W + 16384 + off);
                    ldsm4(Bl, sb + SM_W + 32768 + off);
                    mma_bf16(D3[p * 2 + 0], Ah[kt], Bh + 0);
                    mma_bf16(D3[p * 2 + 0], Al[kt], Bh + 0);
                    mma_bf16(D3[p * 2 + 0], Ah[kt], Bl + 0);
                    mma_bf16(D3[p * 2 + 1], Ah[kt], Bh + 2);
                    mma_bf16(D3[p * 2 + 1], Al[kt], Bh + 2);
                    mma_bf16(D3[p * 2 + 1], Ah[kt], Bl + 2);
                }
            }
            const int jc = (lane & 3) * 2;
#pragma unroll
            for (int nt = 0; nt < 4; nt++) {
                int j0 = nc3 + hh * 32 + nt * 8 + jc;
                int ri = hh * 8 + nt * 2;
                if (vr0) {
                    rmax[ri]     = fmaxf(rmax[ri],     fmaxf(D3[nt][0] + b3s[j0],     0.f));
                    rmax[ri + 1] = fmaxf(rmax[ri + 1], fmaxf(D3[nt][1] + b3s[j0 + 1], 0.f));
                }
                if (vr1) {
                    rmax[ri]     = fmaxf(rmax[ri],     fmaxf(D3[nt][2] + b3s[j0],     0.f));
                    rmax[ri + 1] = fmaxf(rmax[ri + 1], fmaxf(D3[nt][3] + b3s[j0 + 1], 0.f));
                }
            }
        }
    }

    // ---- reduce: lanes sharing lane%4 hold same cols -> butterfly ----
#pragma unroll
    for (int o = 4; o <= 16; o <<= 1)
#pragma unroll
        for (int i = 0; i < 16; i++)
            rmax[i] = fmaxf(rmax[i], __shfl_xor_sync(0xffffffffu, rmax[i], o));
    if (lane < 4) {
        float* red = (float*)(sm + SM_RED);
#pragma unroll
        for (int i = 0; i < 16; i++) {
            int col = nc3 + (i >> 1) * 8 + lane * 2 + (i & 1);
            red[(w & 7) * 128 + col] = rmax[i];
        }
    }
    __syncthreads();
    if (tid < 128) {
        const float* red = (const float*)(sm + SM_RED);
        float m = red[tid];
#pragma unroll
        for (int r = 1; r < 8; r++) m = fmaxf(m, red[r * 128 + tid]);
        outF[bid * 128 + tid] = m;
    }
}

// ======================================================================
extern "C" void kernel_launch(void* const* d_in, const int* in_sizes, int n_in,
                              void* d_out, int out_size)
{
    const float* coords = (const float*)d_in[0];
    const float* feats  = (const float*)d_in[1];
    const int*   cidx   = (const int*)  d_in[2];
    const float* W1 = (const float*)d_in[3];
    const float* b1 = (const float*)d_in[4];
    const float* W2 = (const float*)d_in[5];
    const float* b2 = (const float*)d_in[6];
    const float* W3 = (const float*)d_in[7];
    const float* b3 = (const float*)d_in[8];
    float* out = (float*)d_out;

    cudaFuncSetAttribute((const void*)k_mlp,
                         cudaFuncAttributeMaxDynamicSharedMemorySize, SM_TOTAL);

    k_pack <<<(NPAD + 255) / 256, 256>>>(coords);
    k_P    <<<(NPTS + 63) / 64, 256>>>(coords, feats, W1);
    k_cent <<<(KC * 64) / 256, 256>>>(coords, cidx, W1, b1, out);
    k_prepW<<<1, 512>>>(W2, W3);
    k_ball <<<KC / 8, 256>>>(coords, cidx);
    k_mlp  <<<KC, 512, SM_TOTAL>>>(b2, b3, out + KC * 3);
}

// round 11
// speedup vs baseline: 2.0679x; 1.2528x over previous
#include <cuda_runtime.h>
#include <cuda_bf16.h>
#include <cstdint>

#define NPTS 100000
#define KC   1024
#define NPAD 100352            // 7 * 14336 = 49 * 2048
#define NSEG 7
#define SEGPTS 14336           // 7 tiles of 2048
#define SEGTILES 7

typedef unsigned long long ull;

// ---------------- scratch (static __device__, no allocation) ----------------
__device__ float g_P[NPTS * 64];     // per-point layer-1 partials
__device__ float g_ct[KC * 64];      // per-centroid layer-1 term (b1 - cent@W1c)
__device__ int   g_idx[KC * KC];     // selected neighbor indices
__device__ int   g_cnt[KC];          // valid neighbor counts
__device__ uint4 g_Wimg[3072];       // swizzled bf16 weight images
__device__ float4 g_pts[NPAD];       // packed (x,y,z,||p||^2), padded with sentinels
__device__ float4 g_cq[KC];          // centroid (x,y,z,||c||^2)
__device__ int   g_segcnt[KC * 8];   // per (centroid, segment) hit counts
__device__ int   g_segbase[KC * 8];  // per (centroid, segment) write bases

// ---------------- helpers ----------------
__device__ __forceinline__ ull pack2(float lo, float hi) {
    ull r; asm("mov.b64 %0, {%1, %2};" : "=l"(r) : "f"(lo), "f"(hi)); return r;
}
__device__ __forceinline__ void unpack2(ull v, float& lo, float& hi) {
    asm("mov.b64 {%0, %1}, %2;" : "=f"(lo), "=f"(hi) : "l"(v));
}
__device__ __forceinline__ ull fma2(ull a, ull b, ull c) {
    ull d; asm("fma.rn.f32x2 %0, %1, %2, %3;" : "=l"(d) : "l"(a), "l"(b), "l"(c)); return d;
}
__device__ __forceinline__ ull mul2(ull a, ull b) {
    ull d; asm("mul.rn.f32x2 %0, %1, %2;" : "=l"(d) : "l"(a), "l"(b)); return d;
}
__device__ __forceinline__ ull add2(ull a, ull b) {
    ull d; asm("add.rn.f32x2 %0, %1, %2;" : "=l"(d) : "l"(a), "l"(b)); return d;
}
__device__ __forceinline__ uint32_t smem_u32(const void* p) {
    uint32_t a;
    asm("{ .reg .u64 t; cvta.to.shared.u64 t, %1; cvt.u32.u64 %0, t; }" : "=r"(a) : "l"(p));
    return a;
}
__host__ __device__ __forceinline__ uint32_t swz128(uint32_t b) { return b ^ ((b >> 3) & 0x70); }

// packed squared distance: both halves computed with identical fp32 op
// sequence — used by BOTH count and write passes (predicate consistency).
__device__ __forceinline__ ull d2pair(ull CX, ull CY, ull CZ, ull CC, float4 p) {
    ull PX = pack2(p.x, p.x), PY = pack2(p.y, p.y);
    ull PZ = pack2(p.z, p.z), PW = pack2(p.w, p.w);
    ull dot = mul2(CX, PX);
    dot = fma2(CY, PY, dot);
    dot = fma2(CZ, PZ, dot);
    ull s = add2(CC, PW);
    return fma2(dot, pack2(-2.f, -2.f), s);     // (cc+pp) - 2*dot
}

// bf16 hi/lo split of a float pair, packed as bf16x2 words
__device__ __forceinline__ void split2(float a, float b, uint32_t& hi, uint32_t& lo) {
    __nv_bfloat162 h = __floats2bfloat162_rn(a, b);
    float ra = a - __bfloat162float(h.x);
    float rb = b - __bfloat162float(h.y);
    __nv_bfloat162 l = __floats2bfloat162_rn(ra, rb);
    hi = *reinterpret_cast<uint32_t*>(&h);
    lo = *reinterpret_cast<uint32_t*>(&l);
}

// ---------------- legacy tensor-core primitives (sm_80+, valid on sm_103) ----
__device__ __forceinline__ void ldsm4(uint32_t* r, uint32_t addr) {
    asm volatile("ldmatrix.sync.aligned.m8n8.x4.shared.b16 {%0,%1,%2,%3}, [%4];"
                 : "=r"(r[0]), "=r"(r[1]), "=r"(r[2]), "=r"(r[3]) : "r"(addr));
}
__device__ __forceinline__ void mma_bf16(float* d, const uint32_t* a, const uint32_t* b) {
    asm volatile("mma.sync.aligned.m16n8k16.row.col.f32.bf16.bf16.f32 "
                 "{%0,%1,%2,%3}, {%4,%5,%6,%7}, {%8,%9}, {%0,%1,%2,%3};"
                 : "+f"(d[0]), "+f"(d[1]), "+f"(d[2]), "+f"(d[3])
                 : "r"(a[0]), "r"(a[1]), "r"(a[2]), "r"(a[3]), "r"(b[0]), "r"(b[1]));
}

// ======================================================================
// Stage A0: pack coords + squared norm, padded with far sentinels
// ======================================================================
__global__ __launch_bounds__(256) void k_pack(const float* __restrict__ coords)
{
    int i = blockIdx.x * 256 + threadIdx.x;
    if (i >= NPAD) return;
    float4 v;
    if (i < NPTS) {
        float x = coords[3 * i], y = coords[3 * i + 1], z = coords[3 * i + 2];
        v = make_float4(x, y, z, x * x + y * y + z * z);
    } else {
        v = make_float4(1e9f, 1e9f, 1e9f, 1e9f);
    }
    g_pts[i] = v;
}

// ======================================================================
// Stage A: P[j,:] = coords[j] @ W1[0:3,:] + feats[j] @ W1[3:67,:]  (fp32)
// ======================================================================
__global__ __launch_bounds__(256) void k_P(const float* __restrict__ coords,
                                           const float* __restrict__ feats,
                                           const float* __restrict__ W1)
{
    __shared__ float W1s[67 * 64];
    __shared__ float xs[64 * 68];

    const int tid = threadIdx.x;
    const int row0 = blockIdx.x * 64;

    for (int i = tid; i < 67 * 64; i += 256) W1s[i] = W1[i];
    for (int i = tid; i < 64 * 64; i += 256) {
        int r = i >> 6, c = i & 63; int row = row0 + r;
        xs[r * 68 + 3 + c] = (row < NPTS) ? feats[row * 64 + c] : 0.f;
    }
    for (int i = tid; i < 192; i += 256) {
        int r = i / 3, d = i - 3 * r; int row = row0 + r;
        xs[r * 68 + d] = (row < NPTS) ? coords[row * 3 + d] : 0.f;
    }
    __syncthreads();

    const int r = tid >> 2, seg = tid & 3;
    const int row = row0 + r;
    ull acc[8];
    ull z = pack2(0.f, 0.f);
#pragma unroll
    for (int j = 0; j < 8; j++) acc[j] = z;

    const float* xr = &xs[r * 68];
    for (int k = 0; k < 67; k++) {
        float a = xr[k];
        ull A = pack2(a, a);
        const ull* wr = (const ull*)&W1s[k * 64 + seg * 16];
#pragma unroll
        for (int j = 0; j < 8; j++) acc[j] = fma2(A, wr[j], acc[j]);
    }
    if (row < NPTS) {
        ull* dst = (ull*)&g_P[row * 64 + seg * 16];
#pragma unroll
        for (int j = 0; j < 8; j++) dst[j] = acc[j];
    }
}

// ======================================================================
// Stage B1: centroid coords + ||c||^2 pack + per-centroid layer-1 term
// ======================================================================
__global__ __launch_bounds__(256) void k_cent(const float* __restrict__ coords,
                                              const int* __restrict__ cidx,
                                              const float* __restrict__ W1,
                                              const float* __restrict__ b1,
                                              float* __restrict__ out)
{
    int gid = blockIdx.x * 256 + threadIdx.x;
    if (gid >= KC * 64) return;
    int k = gid >> 6, c = gid & 63;
    int ci = cidx[k];
    float cx = coords[ci * 3 + 0];
    float cy = coords[ci * 3 + 1];
    float cz = coords[ci * 3 + 2];
    g_ct[gid] = b1[c] - (cx * W1[c] + cy * W1[64 + c] + cz * W1[128 + c]);
    if (c < 3) out[k * 3 + c] = coords[ci * 3 + c];
    if (c == 0) g_cq[k] = make_float4(cx, cy, cz, cx * cx + cy * cy + cz * cz);
}

// ======================================================================
// Stage B2: weight prep — [n rows][k=64 bf16] hi/lo images, 128B rows,
// SW128-swizzled; directly ldmatrix-able as mma.sync B fragments.
// ======================================================================
__global__ __launch_bounds__(512) void k_prepW(const float* __restrict__ W2,
                                               const float* __restrict__ W3)
{
    const int tid = threadIdx.x;
    if (tid < 512) {
        int c = tid;
        int n = c >> 3, kc = c & 7;
        uint32_t hi[4], lo[4];
#pragma unroll
        for (int q = 0; q < 4; q++) {
            int k0 = kc * 8 + 2 * q;
            split2(W2[k0 * 64 + n], W2[(k0 + 1) * 64 + n], hi[q], lo[q]);
        }
        int dst = swz128(n * 128 + kc * 16) >> 4;
        g_Wimg[dst]       = make_uint4(hi[0], hi[1], hi[2], hi[3]);
        g_Wimg[512 + dst] = make_uint4(lo[0], lo[1], lo[2], lo[3]);
    }
    for (int c = tid; c < 1024; c += 512) {
        int n = c >> 3, kc = c & 7;
        uint32_t hi[4], lo[4];
#pragma unroll
        for (int q = 0; q < 4; q++) {
            int k0 = kc * 8 + 2 * q;
            split2(W3[k0 * 128 + n], W3[(k0 + 1) * 128 + n], hi[q], lo[q]);
        }
        int dst = swz128(n * 128 + kc * 16) >> 4;
        g_Wimg[1024 + dst] = make_uint4(hi[0], hi[1], hi[2], hi[3]);
        g_Wimg[2048 + dst] = make_uint4(lo[0], lo[1], lo[2], lo[3]);
    }
}

// ======================================================================
// Stage C1a: COUNT — grid (64, 7). Each warp counts hits in one segment
// for TWO centroids (packed f32x2 distances). No serial chains.
// ======================================================================
__global__ __launch_bounds__(256) void k_count()
{
    __shared__ float4 tile[2048];
    const int tid = threadIdx.x;
    const int w = tid >> 5, l = tid & 31;
    const int seg = blockIdx.y;
    const int c0 = (blockIdx.x * 8 + w) * 2;

    float4 A = g_cq[c0], B = g_cq[c0 + 1];
    ull CX = pack2(A.x, B.x), CY = pack2(A.y, B.y);
    ull CZ = pack2(A.z, B.z), CC = pack2(A.w, B.w);

    int cnt0 = 0, cnt1 = 0;
    const int base = seg * SEGPTS;

    for (int t = 0; t < SEGTILES; t++) {
        for (int v = tid; v < 2048; v += 256) tile[v] = g_pts[base + t * 2048 + v];
        __syncthreads();
#pragma unroll 16
        for (int i = 0; i < 64; i++) {
            float4 p = tile[i * 32 + l];
            float da, db;
            unpack2(d2pair(CX, CY, CZ, CC, p), da, db);
            cnt0 += (da <= 0.04f);
            cnt1 += (db <= 0.04f);
        }
        __syncthreads();
    }
#pragma unroll
    for (int o = 16; o; o >>= 1) {
        cnt0 += __shfl_xor_sync(0xffffffffu, cnt0, o);
        cnt1 += __shfl_xor_sync(0xffffffffu, cnt1, o);
    }
    if (l == 0) {
        g_segcnt[c0 * 8 + seg] = cnt0;
        g_segcnt[(c0 + 1) * 8 + seg] = cnt1;
    }
}

// ======================================================================
// Stage C1b: SCAN — per-centroid exclusive prefix over 7 segment counts
// ======================================================================
__global__ __launch_bounds__(256) void k_scan()
{
    int c = blockIdx.x * 256 + threadIdx.x;
    if (c >= KC) return;
    int acc = 0;
#pragma unroll
    for (int s = 0; s < NSEG; s++) {
        int v = g_segcnt[c * 8 + s];
        g_segbase[c * 8 + s] = acc;
        acc += v;
    }
    g_cnt[c] = (acc < KC) ? acc : KC;
}

// ======================================================================
// Stage C1c: WRITE — grid (128, 7). Warp per centroid per segment;
// 3-phase per-tile (ballots -> shfl prefix -> independent writes),
// starting at the precomputed segment base. Bit-identical predicates
// to k_count via d2pair.
// ======================================================================
__global__ __launch_bounds__(256) void k_write()
{
    __shared__ float4 tile[2048];
    const int tid = threadIdx.x;
    const int w = tid >> 5, l = tid & 31;
    const int seg = blockIdx.y;
    const int cid = blockIdx.x * 8 + w;

    int tot = g_segbase[cid * 8 + seg];
    bool skip = (tot >= KC);
    if (!__syncthreads_or(!skip)) return;     // whole block past cutoff

    float4 A = g_cq[cid];
    ull CX = pack2(A.x, A.x), CY = pack2(A.y, A.y);
    ull CZ = pack2(A.z, A.z), CC = pack2(A.w, A.w);
    const int base = seg * SEGPTS;

    for (int t = 0; t < SEGTILES; t++) {
        for (int v = tid; v < 2048; v += 256) tile[v] = g_pts[base + t * 2048 + v];
        __syncthreads();

        if (!skip) {
            // phase 1: 64 independent ballots; word i kept by lane i%32
            uint32_t r0 = 0, r1 = 0;
#pragma unroll
            for (int i = 0; i < 64; i++) {
                float4 p = tile[i * 32 + l];
                float da, db;
                unpack2(d2pair(CX, CY, CZ, CC, p), da, db);
                unsigned bal = __ballot_sync(0xffffffffu, da <= 0.04f);
                if (i < 32) { if (l == i) r0 = bal; }
                else        { if (l == i - 32) r1 = bal; }
            }
            // phase 2: shuffle BOTH regs from source lane, select with reader's l
            uint32_t sa0 = __shfl_sync(0xffffffffu, r0, (2 * l) & 31);
            uint32_t sa1 = __shfl_sync(0xffffffffu, r1, (2 * l) & 31);
            uint32_t sb0 = __shfl_sync(0xffffffffu, r0, (2 * l + 1) & 31);
            uint32_t sb1 = __shfl_sync(0xffffffffu, r1, (2 * l + 1) & 31);
            uint32_t w0 = (l < 16) ? sa0 : sa1;
            uint32_t w1 = (l < 16) ? sb0 : sb1;
            int c0 = __popc(w0), c1 = __popc(w1);
            int s = c0 + c1, incl = s;
#pragma unroll
            for (int o = 1; o < 32; o <<= 1) {
                int t2 = __shfl_up_sync(0xffffffffu, incl, o);
                if (l >= o) incl += t2;
            }
            int b0 = tot + incl - s;
            int b1v = b0 + c0;
            int tile_total = __shfl_sync(0xffffffffu, incl, 31);
            int nlive = __popc(__ballot_sync(0xffffffffu, b0 < KC))
                      + __popc(__ballot_sync(0xffffffffu, b1v < KC));
            // phase 3: independent writes (selectors are loop-uniform)
#pragma unroll 8
            for (int i = 0; i < 64; i++) {
                if (i >= nlive) break;
                unsigned bal = __shfl_sync(0xffffffffu, (i < 32) ? r0 : r1, i & 31);
                int b = __shfl_sync(0xffffffffu, (i & 1) ? b1v : b0, i >> 1);
                if ((bal >> l) & 1u) {
                    int off = b + __popc(bal & ((1u << l) - 1u));
                    if (off < KC) g_idx[cid * KC + off] = base + t * 2048 + i * 32 + l;
                }
            }
            tot += tile_total;
            if (tot >= KC) skip = true;
        }
        __syncthreads();
    }
}

// ======================================================================
// Stage D: per-centroid MLP via mma.sync bf16 hi/lo split (3-pass),
// fp32 accumulation. One 512-thread block per centroid, 128-row tiles.
// ======================================================================
#define SM_AH  0          // [128 m][64 k] bf16 hi, 128B rows, swizzled (16KB)
#define SM_AL  16384      // lo (16KB)
#define SM_W   32768      // W2h 8K | W2l 8K | W3h 16K | W3l 16K  -> ends 81920
#define SM_CT  81920
#define SM_B2  82176
#define SM_B3  82432
#define SM_RED 82944      // 8 x 128 floats (4KB)
#define SM_TOTAL 87040

__global__ void __launch_bounds__(512, 1)
k_mlp(const float* __restrict__ b2g, const float* __restrict__ b3g,
      float* __restrict__ outF)
{
    extern __shared__ char sm[];
    const uint32_t sb = smem_u32(sm);
    const int tid = threadIdx.x, bid = blockIdx.x;
    const int w = tid >> 5, lane = tid & 31;

    {   // weight + bias + ct staging
        uint4* dst = (uint4*)(sm + SM_W);
        for (int i = tid; i < 3072; i += 512) dst[i] = g_Wimg[i];
        if (tid < 64)       ((float*)(sm + SM_CT))[tid] = g_ct[bid * 64 + tid];
        else if (tid < 128) ((float*)(sm + SM_B2))[tid - 64] = b2g[tid - 64];
        else if (tid < 256) ((float*)(sm + SM_B3))[tid - 128] = b3g[tid - 128];
    }
    const int cnt = g_cnt[bid];
    __syncthreads();

    const int gr = tid >> 2, gseg = tid & 3;
    const float* cts = (const float*)(sm + SM_CT);
    const float* b2s = (const float*)(sm + SM_B2);
    const float* b3s = (const float*)(sm + SM_B3);

    const int mrow = (w & 7) * 16;
    const int nc2  = (w >> 3) * 32;
    const int nc3  = (w >> 3) * 64;
    const uint32_t a_row  = mrow + (lane & 15);
    const uint32_t a_half = ((lane >> 4) & 1) * 16;
    const uint32_t b_nrow = (lane & 7) + ((lane >> 4) & 1) * 8;
    const uint32_t b_koff = ((lane >> 3) & 1) * 16;

    float rmax[16];
#pragma unroll
    for (int i = 0; i < 16; i++) rmax[i] = 0.f;

    for (int t = 0; t * 128 < cnt; t++) {
        // ---- gather + layer1 (relu(P[idx]+ct)), bf16-split -> Ah/Al ----
        {
            const int row = t * 128 + gr;
            float x[16];
            if (row < cnt) {
                int j = g_idx[bid * KC + row];
                const float4* Pp = (const float4*)(g_P + j * 64 + gseg * 16);
#pragma unroll
                for (int q = 0; q < 4; q++) {
                    float4 v = __ldg(Pp + q);
                    float4 c = *(const float4*)&cts[gseg * 16 + q * 4];
                    x[q * 4 + 0] = fmaxf(v.x + c.x, 0.f);
                    x[q * 4 + 1] = fmaxf(v.y + c.y, 0.f);
                    x[q * 4 + 2] = fmaxf(v.z + c.z, 0.f);
                    x[q * 4 + 3] = fmaxf(v.w + c.w, 0.f);
                }
            } else {
#pragma unroll
                for (int i = 0; i < 16; i++) x[i] = 0.f;
            }
            uint32_t hi[8], lo[8];
#pragma unroll
            for (int q = 0; q < 8; q++) split2(x[2 * q], x[2 * q + 1], hi[q], lo[q]);
            uint32_t b0 = gr * 128 + gseg * 32;
            uint32_t s0 = swz128(b0), s1 = swz128(b0 + 16);
            *(uint4*)(sm + SM_AH + s0) = make_uint4(hi[0], hi[1], hi[2], hi[3]);
            *(uint4*)(sm + SM_AH + s1) = make_uint4(hi[4], hi[5], hi[6], hi[7]);
            *(uint4*)(sm + SM_AL + s0) = make_uint4(lo[0], lo[1], lo[2], lo[3]);
            *(uint4*)(sm + SM_AL + s1) = make_uint4(lo[4], lo[5], lo[6], lo[7]);
        }
        __syncthreads();

        // ---- A fragments (h1) ----
        uint32_t Ah[4][4], Al[4][4];
#pragma unroll
        for (int kt = 0; kt < 4; kt++) {
            uint32_t off = swz128(a_row * 128 + kt * 32 + a_half);
            ldsm4(Ah[kt], sb + SM_AH + off);
            ldsm4(Al[kt], sb + SM_AL + off);
        }
        __syncthreads();

        // ---- layer2: per warp 16x32, 3-pass bf16 ----
        float D[4][4];
#pragma unroll
        for (int i = 0; i < 4; i++)
#pragma unroll
            for (int j = 0; j < 4; j++) D[i][j] = 0.f;
#pragma unroll
        for (int p = 0; p < 2; p++) {
#pragma unroll
            for (int kt = 0; kt < 4; kt++) {
                uint32_t off = swz128((nc2 + p * 16 + b_nrow) * 128 + kt * 32 + b_koff);
                uint32_t Bh[4], Bl[4];
                ldsm4(Bh, sb + SM_W + off);
                ldsm4(Bl, sb + SM_W + 8192 + off);
                mma_bf16(D[p * 2 + 0], Ah[kt], Bh + 0);
                mma_bf16(D[p * 2 + 0], Al[kt], Bh + 0);
                mma_bf16(D[p * 2 + 0], Ah[kt], Bl + 0);
                mma_bf16(D[p * 2 + 1], Ah[kt], Bh + 2);
                mma_bf16(D[p * 2 + 1], Al[kt], Bh + 2);
                mma_bf16(D[p * 2 + 1], Ah[kt], Bl + 2);
            }
        }

        // ---- epilogue2: relu(D+b2), split, store h2 into Ah/Al ----
        {
            const int r0 = mrow + (lane >> 2);
            const int jc = (lane & 3) * 2;
#pragma unroll
            for (int nt = 0; nt < 4; nt++) {
                int j0 = nc2 + nt * 8 + jc;
                float v0 = fmaxf(D[nt][0] + b2s[j0],     0.f);
                float v1 = fmaxf(D[nt][1] + b2s[j0 + 1], 0.f);
                float v2 = fmaxf(D[nt][2] + b2s[j0],     0.f);
                float v3 = fmaxf(D[nt][3] + b2s[j0 + 1], 0.f);
                uint32_t h0, l0, h1, l1;
                split2(v0, v1, h0, l0);
                split2(v2, v3, h1, l1);
                uint32_t o0 = swz128(r0 * 128 + j0 * 2);
                uint32_t o1 = swz128((r0 + 8) * 128 + j0 * 2);
                *(uint32_t*)(sm + SM_AH + o0) = h0;
                *(uint32_t*)(sm + SM_AL + o0) = l0;
                *(uint32_t*)(sm + SM_AH + o1) = h1;
                *(uint32_t*)(sm + SM_AL + o1) = l1;
            }
        }
        __syncthreads();

        // ---- A fragments (h2) ----
#pragma unroll
        for (int kt = 0; kt < 4; kt++) {
            uint32_t off = swz128(a_row * 128 + kt * 32 + a_half);
            ldsm4(Ah[kt], sb + SM_AH + off);
            ldsm4(Al[kt], sb + SM_AL + off);
        }
        __syncthreads();

        // ---- layer3 (per warp 16x64, two 32-col halves) + masked max ----
        const int r0g = t * 128 + mrow + (lane >> 2);
        const bool vr0 = (r0g < cnt), vr1 = (r0g + 8 < cnt);
#pragma unroll
        for (int hh = 0; hh < 2; hh++) {
            float D3[4][4];
#pragma unroll
            for (int i = 0; i < 4; i++)
#pragma unroll
                for (int j = 0; j < 4; j++) D3[i][j] = 0.f;
#pragma unroll
            for (int p = 0; p < 2; p++) {
#pragma unroll
                for (int kt = 0; kt < 4; kt++) {
                    uint32_t off = swz128((nc3 + hh * 32 + p * 16 + b_nrow) * 128 + kt * 32 + b_koff);
                    uint32_t Bh[4], Bl[4];
                    ldsm4(Bh, sb + SM_W + 16384 + off);
                    ldsm4(Bl, sb + SM_W + 32768 + off);
                    mma_bf16(D3[p * 2 + 0], Ah[kt], Bh + 0);
                    mma_bf16(D3[p * 2 + 0], Al[kt], Bh + 0);
                    mma_bf16(D3[p * 2 + 0], Ah[kt], Bl + 0);
                    mma_bf16(D3[p * 2 + 1], Ah[kt], Bh + 2);
                    mma_bf16(D3[p * 2 + 1], Al[kt], Bh + 2);
                    mma_bf16(D3[p * 2 + 1], Ah[kt], Bl + 2);
                }
            }
            const int jc = (lane & 3) * 2;
#pragma unroll
            for (int nt = 0; nt < 4; nt++) {
                int j0 = nc3 + hh * 32 + nt * 8 + jc;
                int ri = hh * 8 + nt * 2;
                if (vr0) {
                    rmax[ri]     = fmaxf(rmax[ri],     fmaxf(D3[nt][0] + b3s[j0],     0.f));
                    rmax[ri + 1] = fmaxf(rmax[ri + 1], fmaxf(D3[nt][1] + b3s[j0 + 1], 0.f));
                }
                if (vr1) {
                    rmax[ri]     = fmaxf(rmax[ri],     fmaxf(D3[nt][2] + b3s[j0],     0.f));
                    rmax[ri + 1] = fmaxf(rmax[ri + 1], fmaxf(D3[nt][3] + b3s[j0 + 1], 0.f));
                }
            }
        }
    }

    // ---- reduce: lanes sharing lane%4 hold same cols -> butterfly ----
#pragma unroll
    for (int o = 4; o <= 16; o <<= 1)
#pragma unroll
        for (int i = 0; i < 16; i++)
            rmax[i] = fmaxf(rmax[i], __shfl_xor_sync(0xffffffffu, rmax[i], o));
    if (lane < 4) {
        float* red = (float*)(sm + SM_RED);
#pragma unroll
        for (int i = 0; i < 16; i++) {
            int col = nc3 + (i >> 1) * 8 + lane * 2 + (i & 1);
            red[(w & 7) * 128 + col] = rmax[i];
        }
    }
    __syncthreads();
    if (tid < 128) {
        const float* red = (const float*)(sm + SM_RED);
        float m = red[tid];
#pragma unroll
        for (int r = 1; r < 8; r++) m = fmaxf(m, red[r * 128 + tid]);
        outF[bid * 128 + tid] = m;
    }
}

// ======================================================================
extern "C" void kernel_launch(void* const* d_in, const int* in_sizes, int n_in,
                              void* d_out, int out_size)
{
    const float* coords = (const float*)d_in[0];
    const float* feats  = (const float*)d_in[1];
    const int*   cidx   = (const int*)  d_in[2];
    const float* W1 = (const float*)d_in[3];
    const float* b1 = (const float*)d_in[4];
    const float* W2 = (const float*)d_in[5];
    const float* b2 = (const float*)d_in[6];
    const float* W3 = (const float*)d_in[7];
    const float* b3 = (const float*)d_in[8];
    float* out = (float*)d_out;

    cudaFuncSetAttribute((const void*)k_mlp,
                         cudaFuncAttributeMaxDynamicSharedMemorySize, SM_TOTAL);

    k_pack <<<(NPAD + 255) / 256, 256>>>(coords);
    k_P    <<<(NPTS + 63) / 64, 256>>>(coords, feats, W1);
    k_cent <<<(KC * 64) / 256, 256>>>(coords, cidx, W1, b1, out);
    k_prepW<<<1, 512>>>(W2, W3);
    k_count<<<dim3(64, NSEG), 256>>>();
    k_scan <<<4, 256>>>();
    k_write<<<dim3(128, NSEG), 256>>>();
    k_mlp  <<<KC, 512, SM_TOTAL>>>(b2, b3, out + KC * 3);
}